// round 13
// baseline (speedup 1.0000x reference)
#include <cuda_runtime.h>

// Windowed local attention, k=7, H=W=256, C=32, fp32.
// R9 algorithm (thread = vertical pixel-pair x window-row half, 56 accs,
// shfl_xor(16) combines) repackaged: tile 8x8 px, 64 threads, grid 1024
// -> wave-quantization loss ~1% (vs 16% at grid 256). Halo 14x14, row
// stride 20: lane bank = 8*pry + 16*half + px -> all 32 distinct.

#define H_IMG 256
#define W_IMG 256
#define C 32
#define K 7
#define PAD 3
#define TX 8
#define TY 8
#define HW 14               // used halo cols
#define HWS 20              // padded row stride (4*20 % 32 == 16)
#define HH 14               // TY + 6
#define CHST (HH * HWS)     // 280 floats per channel
#define NTHREADS 64
#define SMEM_BYTES (C * CHST * 4)   // 35840

// Stage one tensor's halo: [c][row*HWS + col], zero-padded OOB.
__device__ __forceinline__ void stage_halo(float* __restrict__ buf,
                                           const float* __restrict__ src,
                                           int bx, int by, int tid) {
    for (int p = tid; p < HW * HH; p += NTHREADS) {
        int hp = p / HW;
        int wp = p - hp * HW;
        int gw = bx * TX - PAD + wp;
        int gh = by * TY - PAD + hp;
        bool ok = (gw >= 0) && (gw < W_IMG) && (gh >= 0) && (gh < H_IMG);
        int sa = hp * HWS + wp;
        int ga = ((gh << 8) + gw) * C;
        #pragma unroll
        for (int g = 0; g < 8; g++) {
            float4 r = make_float4(0.f, 0.f, 0.f, 0.f);
            if (ok) r = *reinterpret_cast<const float4*>(src + ga + (g << 2));
            float* d = buf + (g << 2) * CHST + sa;
            d[0 * CHST] = r.x;
            d[1 * CHST] = r.y;
            d[2 * CHST] = r.z;
            d[3 * CHST] = r.w;
        }
    }
}

__global__ __launch_bounds__(NTHREADS, 6)
void local_attn_kernel(const float* __restrict__ main_in,
                       const float* __restrict__ ref_in,
                       const float* __restrict__ val_in,
                       float* __restrict__ out) {
    extern __shared__ float smem[];

    const int tid  = threadIdx.x;
    const int bx   = blockIdx.x, by = blockIdx.y;
    const int w    = tid >> 5;            // warp 0..1: pair-rows 2w..2w+1
    const int lane = tid & 31;
    const int half = lane >> 4;           // 0: union rows 0-3, 1: rows 4-7
    const int sub  = lane & 15;
    const int pry  = sub >> 3;            // pair-row within warp
    const int px   = sub & 7;             // tile col 0..7
    const int pr   = 2 * w + pry;         // pair-row 0..3

    const int sbase = (2 * pr + 4 * half) * HWS + px;

    const int gy0   = by * TY + 2 * pr;
    const int gpix0 = ((gy0 << 8) + bx * TX + px) * C;   // pixel0 (row 2pr)
    const int gpix1 = gpix0 + W_IMG * C;                 // pixel1 (row 2pr+1)
    const int gprim = half ? gpix1 : gpix0;              // primary pixel
    const int gseco = half ? gpix0 : gpix1;              // secondary pixel

    // ---- Stage ref halo ----
    stage_halo(smem, ref_in, bx, by, tid);
    __syncthreads();

    // ---- Pass 1: prim/seco partial scores over 4 local rows x 7 cols ----
    // prim[r*7+dw]: primary pixel's contribution at local row r.
    // seco[r*7+dw]: secondary pixel's (half A: valid r>=1, half B: r<=2).
    float prim[28], seco[28];
    #pragma unroll
    for (int i = 0; i < 28; i++) { prim[i] = 0.f; seco[i] = 0.f; }

    #pragma unroll
    for (int cc = 0; cc < 4; cc++) {                 // 8-channel chunks
        float qp[8], qs[8];
        #pragma unroll
        for (int i = 0; i < 2; i++) {
            float4 a = *reinterpret_cast<const float4*>(main_in + gprim + cc * 8 + 4 * i);
            float4 b = *reinterpret_cast<const float4*>(main_in + gseco + cc * 8 + 4 * i);
            qp[4 * i + 0] = a.x; qp[4 * i + 1] = a.y; qp[4 * i + 2] = a.z; qp[4 * i + 3] = a.w;
            qs[4 * i + 0] = b.x; qs[4 * i + 1] = b.y; qs[4 * i + 2] = b.z; qs[4 * i + 3] = b.w;
        }
        #pragma unroll
        for (int c = 0; c < 8; c++) {
            const float* base = smem + (cc * 8 + c) * CHST + sbase;
            #pragma unroll
            for (int r = 0; r < 4; r++) {
                #pragma unroll
                for (int dw = 0; dw < K; dw++) {
                    float v = base[r * HWS + dw];
                    prim[r * 7 + dw] = fmaf(v, qp[c], prim[r * 7 + dw]);
                    seco[r * 7 + dw] = fmaf(v, qs[c], seco[r * 7 + dw]);
                }
            }
        }
    }

    // ---- Split softmax: combine pair lanes via shfl_xor(16) ----
    // (OOB halo positions carry score 0 and are included, matching reference.)
    float lmP = -1e30f, lmS = -1e30f;
    #pragma unroll
    for (int i = 0; i < 28; i++) lmP = fmaxf(lmP, prim[i]);
    #pragma unroll
    for (int r = 0; r < 4; r++) {
        bool valid = half ? (r <= 2) : (r >= 1);
        #pragma unroll
        for (int dw = 0; dw < K; dw++) {
            float s = valid ? seco[r * 7 + dw] : -1e30f;
            lmS = fmaxf(lmS, s);
        }
    }
    float gmP = fmaxf(lmP, __shfl_xor_sync(0xffffffffu, lmS, 16));
    float gmS = fmaxf(lmS, __shfl_xor_sync(0xffffffffu, lmP, 16));

    float lsP = 0.f, lsS = 0.f;
    #pragma unroll
    for (int i = 0; i < 28; i++) {
        prim[i] = __expf(prim[i] - gmP);
        lsP += prim[i];
    }
    #pragma unroll
    for (int r = 0; r < 4; r++) {
        bool valid = half ? (r <= 2) : (r >= 1);
        #pragma unroll
        for (int dw = 0; dw < K; dw++) {
            float e = valid ? __expf(seco[r * 7 + dw] - gmS) : 0.f;
            seco[r * 7 + dw] = e;
            lsS += e;
        }
    }
    float gsP = lsP + __shfl_xor_sync(0xffffffffu, lsS, 16);
    float gsS = lsS + __shfl_xor_sync(0xffffffffu, lsP, 16);
    float ivP = 1.f / gsP, ivS = 1.f / gsS;
    #pragma unroll
    for (int i = 0; i < 28; i++) { prim[i] *= ivP; seco[i] *= ivS; }
    // garbage seco rows now hold weight 0 -> pass 2 is branch-free.

    // ---- Stage val halo (reuse buffer) ----
    __syncthreads();
    stage_halo(smem, val_in, bx, by, tid);
    __syncthreads();

    // ---- Pass 2: partial outputs; combine with partner lane; store ----
    #pragma unroll
    for (int g = 0; g < 8; g++) {
        float oP[4] = {0.f, 0.f, 0.f, 0.f};
        float oS[4] = {0.f, 0.f, 0.f, 0.f};
        #pragma unroll
        for (int c = 0; c < 4; c++) {
            const float* base = smem + ((g << 2) + c) * CHST + sbase;
            #pragma unroll
            for (int r = 0; r < 4; r++) {
                #pragma unroll
                for (int dw = 0; dw < K; dw++) {
                    float v = base[r * HWS + dw];
                    oP[c] = fmaf(v, prim[r * 7 + dw], oP[c]);
                    oS[c] = fmaf(v, seco[r * 7 + dw], oS[c]);
                }
            }
        }
        // partner's oS is the other half of my primary pixel
        float f0 = oP[0] + __shfl_xor_sync(0xffffffffu, oS[0], 16);
        float f1 = oP[1] + __shfl_xor_sync(0xffffffffu, oS[1], 16);
        float f2 = oP[2] + __shfl_xor_sync(0xffffffffu, oS[2], 16);
        float f3 = oP[3] + __shfl_xor_sync(0xffffffffu, oS[3], 16);
        *reinterpret_cast<float4*>(out + gprim + (g << 2)) =
            make_float4(f0, f1, f2, f3);
    }
}

extern "C" void kernel_launch(void* const* d_in, const int* in_sizes, int n_in,
                              void* d_out, int out_size) {
    const float* main_in = (const float*)d_in[0];
    const float* ref_in  = (const float*)d_in[1];
    const float* val_in  = (const float*)d_in[2];
    float* out = (float*)d_out;

    cudaFuncSetAttribute(local_attn_kernel,
                         cudaFuncAttributeMaxDynamicSharedMemorySize, SMEM_BYTES);

    dim3 grid(W_IMG / TX, H_IMG / TY);
    local_attn_kernel<<<grid, NTHREADS, SMEM_BYTES>>>(main_in, ref_in, val_in, out);
}

// round 14
// speedup vs baseline: 1.1008x; 1.1008x over previous
#include <cuda_runtime.h>

// Windowed local attention, k=7, H=W=256, C=32, fp32.
// Thread = (2x2 pixel QUAD, union-row half). The quad's 8x8 union window is
// row-partitioned between partner lanes (xor 16): each thread's 4 rows yield
// COMPLETE scores for those rows (no per-score combine). 16 loads/px/ch/pass
// vs 28 for vertical pairs. Shell kept boost-friendly: tile 32x8, 128 thr,
// grid 256, 71.7KB smem, launch_bounds(128,3).

#define H_IMG 256
#define W_IMG 256
#define C 32
#define K 7
#define PAD 3
#define TX 32
#define TY 8
#define HW 38               // used halo cols
#define HWS 40              // padded row stride
#define HH 14               // TY + 6
#define CHST (HH * HWS)     // 560 floats per channel
#define NTHREADS 128
#define SMEM_BYTES (C * CHST * 4)   // 71680

// Stage one tensor's halo: [c][row*HWS + col], zero-padded OOB.
__device__ __forceinline__ void stage_halo(float* __restrict__ buf,
                                           const float* __restrict__ src,
                                           int bx, int by, int tid) {
    for (int p = tid; p < HW * HH; p += NTHREADS) {
        int hp = p / HW;
        int wp = p - hp * HW;
        int gw = bx * TX - PAD + wp;
        int gh = by * TY - PAD + hp;
        bool ok = (gw >= 0) && (gw < W_IMG) && (gh >= 0) && (gh < H_IMG);
        int sa = hp * HWS + wp;
        int ga = ((gh << 8) + gw) * C;
        #pragma unroll
        for (int g = 0; g < 8; g++) {
            float4 r = make_float4(0.f, 0.f, 0.f, 0.f);
            if (ok) r = *reinterpret_cast<const float4*>(src + ga + (g << 2));
            float* d = buf + (g << 2) * CHST + sa;
            d[0 * CHST] = r.x;
            d[1 * CHST] = r.y;
            d[2 * CHST] = r.z;
            d[3 * CHST] = r.w;
        }
    }
}

__global__ __launch_bounds__(NTHREADS, 3)
void local_attn_kernel(const float* __restrict__ main_in,
                       const float* __restrict__ ref_in,
                       const float* __restrict__ val_in,
                       float* __restrict__ out) {
    extern __shared__ float smem[];

    const int tid  = threadIdx.x;
    const int bx   = blockIdx.x, by = blockIdx.y;
    const int w    = tid >> 5;            // quad row 0..3 (px rows 2w, 2w+1)
    const int lane = tid & 31;
    const int qc   = lane & 15;           // quad col (px cols 2qc, 2qc+1)
    const int half = lane >> 4;           // union-row half: rows 4h..4h+3

    // This thread's 4 union rows x 8 cols start here:
    const int sbase = (2 * w + 4 * half) * HWS + 2 * qc;

    // Quad pixels p = py*2 + px_
    int gp[4];
    #pragma unroll
    for (int p = 0; p < 4; p++) {
        int gy = by * TY + 2 * w + (p >> 1);
        int gx = bx * TX + 2 * qc + (p & 1);
        gp[p] = ((gy << 8) + gx) * C;
    }

    // ---- Stage ref halo ----
    stage_halo(smem, ref_in, bx, by, tid);
    __syncthreads();

    // ---- Pass 1: complete scores for this thread's rows ----
    // sc[p*28 + ur*7 + dw]: score of pixel p at window row (4*half+ur - py).
    // Invalid: half==0 & py==1 & ur==0;  half==1 & py==0 & ur==3.
    float sc[112];
    #pragma unroll
    for (int i = 0; i < 112; i++) sc[i] = 0.f;

    #pragma unroll
    for (int cc = 0; cc < 8; cc++) {               // 4-channel chunks
        float qr[4][4];
        #pragma unroll
        for (int p = 0; p < 4; p++) {
            float4 t = *reinterpret_cast<const float4*>(main_in + gp[p] + cc * 4);
            qr[p][0] = t.x; qr[p][1] = t.y; qr[p][2] = t.z; qr[p][3] = t.w;
        }
        #pragma unroll
        for (int c = 0; c < 4; c++) {
            const float* bp = smem + (cc * 4 + c) * CHST + sbase;
            #pragma unroll
            for (int ur = 0; ur < 4; ur++) {
                float2 v0 = *reinterpret_cast<const float2*>(bp + ur * HWS + 0);
                float2 v1 = *reinterpret_cast<const float2*>(bp + ur * HWS + 2);
                float2 v2 = *reinterpret_cast<const float2*>(bp + ur * HWS + 4);
                float2 v3 = *reinterpret_cast<const float2*>(bp + ur * HWS + 6);
                float vv[8] = {v0.x, v0.y, v1.x, v1.y, v2.x, v2.y, v3.x, v3.y};
                #pragma unroll
                for (int p = 0; p < 4; p++) {
                    #pragma unroll
                    for (int dw = 0; dw < K; dw++) {
                        int idx = p * 28 + ur * 7 + dw;
                        sc[idx] = fmaf(vv[dw + (p & 1)], qr[p][c], sc[idx]);
                    }
                }
            }
        }
    }

    // ---- Softmax per pixel; partner lane (xor 16) holds the other rows ----
    // (OOB halo positions carry score 0 and are included, matching reference.)
    #pragma unroll
    for (int p = 0; p < 4; p++) {
        int bad = half ? ((p < 2) ? 3 : -1) : ((p >= 2) ? 0 : -1);
        float m = -1e30f;
        #pragma unroll
        for (int ur = 0; ur < 4; ur++) {
            #pragma unroll
            for (int dw = 0; dw < K; dw++) {
                float v = (ur == bad) ? -1e30f : sc[p * 28 + ur * 7 + dw];
                m = fmaxf(m, v);
            }
        }
        m = fmaxf(m, __shfl_xor_sync(0xffffffffu, m, 16));
        float s = 0.f;
        #pragma unroll
        for (int ur = 0; ur < 4; ur++) {
            #pragma unroll
            for (int dw = 0; dw < K; dw++) {
                int idx = p * 28 + ur * 7 + dw;
                float e = (ur == bad) ? 0.f : __expf(sc[idx] - m);
                sc[idx] = e;
                s += e;
            }
        }
        s += __shfl_xor_sync(0xffffffffu, s, 16);
        float iv = 1.f / s;
        #pragma unroll
        for (int i = 0; i < 28; i++) sc[p * 28 + i] *= iv;
    }

    // ---- Stage val halo (reuse buffer) ----
    __syncthreads();
    stage_halo(smem, val_in, bx, by, tid);
    __syncthreads();

    // ---- Pass 2: partial outputs over own rows; combine via xor 16 ----
    #pragma unroll
    for (int g = 0; g < 8; g++) {
        float acc[16];                              // [p][c]
        #pragma unroll
        for (int i = 0; i < 16; i++) acc[i] = 0.f;

        #pragma unroll
        for (int c = 0; c < 4; c++) {
            const float* bp = smem + (g * 4 + c) * CHST + sbase;
            #pragma unroll
            for (int ur = 0; ur < 4; ur++) {
                float2 v0 = *reinterpret_cast<const float2*>(bp + ur * HWS + 0);
                float2 v1 = *reinterpret_cast<const float2*>(bp + ur * HWS + 2);
                float2 v2 = *reinterpret_cast<const float2*>(bp + ur * HWS + 4);
                float2 v3 = *reinterpret_cast<const float2*>(bp + ur * HWS + 6);
                float vv[8] = {v0.x, v0.y, v1.x, v1.y, v2.x, v2.y, v3.x, v3.y};
                #pragma unroll
                for (int p = 0; p < 4; p++) {
                    #pragma unroll
                    for (int dw = 0; dw < K; dw++) {
                        acc[p * 4 + c] = fmaf(vv[dw + (p & 1)],
                                              sc[p * 28 + ur * 7 + dw],
                                              acc[p * 4 + c]);
                    }
                }
            }
        }
        #pragma unroll
        for (int i = 0; i < 16; i++)
            acc[i] += __shfl_xor_sync(0xffffffffu, acc[i], 16);

        // half A stores py0 pixels (p=0,1); half B stores py1 (p=2,3)
        int p0 = half * 2;
        *reinterpret_cast<float4*>(out + gp[p0] + g * 4) =
            make_float4(acc[p0 * 4 + 0], acc[p0 * 4 + 1],
                        acc[p0 * 4 + 2], acc[p0 * 4 + 3]);
        *reinterpret_cast<float4*>(out + gp[p0 + 1] + g * 4) =
            make_float4(acc[(p0 + 1) * 4 + 0], acc[(p0 + 1) * 4 + 1],
                        acc[(p0 + 1) * 4 + 2], acc[(p0 + 1) * 4 + 3]);
    }
}

extern "C" void kernel_launch(void* const* d_in, const int* in_sizes, int n_in,
                              void* d_out, int out_size) {
    const float* main_in = (const float*)d_in[0];
    const float* ref_in  = (const float*)d_in[1];
    const float* val_in  = (const float*)d_in[2];
    float* out = (float*)d_out;

    cudaFuncSetAttribute(local_attn_kernel,
                         cudaFuncAttributeMaxDynamicSharedMemorySize, SMEM_BYTES);

    dim3 grid(W_IMG / TX, H_IMG / TY);
    local_attn_kernel<<<grid, NTHREADS, SMEM_BYTES>>>(main_in, ref_in, val_in, out);
}